// round 9
// baseline (speedup 1.0000x reference)
#include <cuda_runtime.h>
#include <math.h>

#define N_ANCH 15130
#define BATCH  32
#define NCLS   81
#define C      80      // foreground classes (1..80)
#define K      200
#define CK     (C * K) // 16000
#define CONF   0.05f
#define IOUT   0.5f
#define CAP2   2048    // per-class candidate capacity (mean ~410, sd ~20 -> 80 sigma safe)

// ---- scratch (device globals; no runtime allocation allowed) ----
__device__ float4             g_boxes[BATCH * N_ANCH];            // decoded ltrb
__device__ unsigned long long g_cand[(size_t)BATCH * C * CAP2];   // (~ord(score)<<32)|anchor
__device__ int                g_cnt[BATCH * C];                   // per (b,c) candidate count
__device__ unsigned           g_u[BATCH * CK];                    // kept keys: ~ord(score), or ~0
__device__ float4             g_kb[BATCH * CK];                   // per-class top-k boxes

// monotonic float->uint mapping (ascending), and its exact inverse
__device__ __forceinline__ unsigned ford(float f) {
    unsigned u = __float_as_uint(f);
    return (u & 0x80000000u) ? ~u : (u | 0x80000000u);
}
__device__ __forceinline__ float finv(unsigned v) {
    unsigned b = (v & 0x80000000u) ? (v & 0x7FFFFFFFu) : ~v;
    return __uint_as_float(b);
}

// ============================================================
// Kernel 0: zero per-cell counters (graph replays need this every launch)
// ============================================================
__global__ void init_kernel() {
    int i = blockIdx.x * blockDim.x + threadIdx.x;
    if (i < BATCH * C) g_cnt[i] = 0;
}

// ============================================================
// Kernel 1: decode boxes + softmax + fused threshold-compaction
// ============================================================
__global__ void decode_kernel(const float* __restrict__ bb,
                              const float* __restrict__ sc,
                              const float* __restrict__ sxy_p,
                              const float* __restrict__ swh_p,
                              const float4* __restrict__ db) {
    int n = blockIdx.x * blockDim.x + threadIdx.x;
    int b = blockIdx.y;
    if (n >= N_ANCH) return;

    float sxy = sxy_p[0], swh = swh_p[0];
    float4 d = db[n];   // (dx, dy, dw, dh)

    const float* bp = bb + (size_t)b * 4 * N_ANCH + n;
    float x = bp[0]          * sxy * d.z + d.x;
    float y = bp[N_ANCH]     * sxy * d.w + d.y;
    float w = expf(bp[2 * N_ANCH] * swh) * d.z;
    float h = expf(bp[3 * N_ANCH] * swh) * d.w;

    g_boxes[(size_t)b * N_ANCH + n] =
        make_float4(x - 0.5f * w, y - 0.5f * h, x + 0.5f * w, y + 0.5f * h);

    // softmax over 81 classes, fully register-resident
    float v[NCLS];
    const float* sp = sc + (size_t)b * NCLS * N_ANCH + n;
#pragma unroll
    for (int cc = 0; cc < NCLS; cc++) v[cc] = sp[(size_t)cc * N_ANCH];
    float m = v[0];
#pragma unroll
    for (int cc = 1; cc < NCLS; cc++) m = fmaxf(m, v[cc]);
    float s = 0.f;
#pragma unroll
    for (int cc = 0; cc < NCLS; cc++) { v[cc] = expf(v[cc] - m); s += v[cc]; }
    float inv = 1.0f / s;

    // emit candidates for foreground classes (prob > CONF)
#pragma unroll
    for (int cc = 1; cc < NCLS; cc++) {
        float p = v[cc] * inv;
        if (p > CONF) {
            int cell = b * C + (cc - 1);
            int pos = atomicAdd(&g_cnt[cell], 1);
            if (pos < CAP2)
                g_cand[(size_t)cell * CAP2 + pos] =
                    ((unsigned long long)(~ford(p)) << 32) | (unsigned)n;
        }
    }
}

// ============================================================
// Kernel 2: per (batch, class): sort candidates -> greedy NMS
// ============================================================
__global__ void nms_kernel() {
    int c = blockIdx.x, b = blockIdx.y;
    int tid = threadIdx.x, nt = blockDim.x;
    int cell = b * C + c;

    __shared__ unsigned long long keys[CAP2];
    __shared__ float4 s_bx[K];
    __shared__ float  s_sc[K];
    __shared__ float  s_ar[K];
    __shared__ int    s_keep[K];

    int cnt = min(g_cnt[cell], CAP2);
    int m = 256;
    while (m < cnt) m <<= 1;   // <= CAP2

    const unsigned long long* cand = g_cand + (size_t)cell * CAP2;
    for (int i = tid; i < m; i += nt)
        keys[i] = (i < cnt) ? cand[i] : 0xFFFFFFFFFFFFFFFFULL;
    __syncthreads();

    // bitonic sort ascending on (~ord(score), idx) => score desc, idx asc
    if (cnt > 1) {
        for (int k = 2; k <= m; k <<= 1) {
            for (int j = k >> 1; j > 0; j >>= 1) {
                for (int i = tid; i < m; i += nt) {
                    int ixj = i ^ j;
                    if (ixj > i) {
                        bool up = ((i & k) == 0);
                        unsigned long long a = keys[i], d2 = keys[ixj];
                        if ((a > d2) == up) { keys[i] = d2; keys[ixj] = a; }
                    }
                }
                __syncthreads();
            }
        }
    }

    int nn = min(cnt, K);
    for (int r = tid; r < K; r += nt) {
        if (r < nn) {
            unsigned long long key = keys[r];
            unsigned idx = (unsigned)(key & 0xFFFFFFFFu);
            float4 bx = g_boxes[(size_t)b * N_ANCH + idx];
            s_bx[r] = bx;
            s_ar[r] = (bx.z - bx.x) * (bx.w - bx.y);
            s_sc[r] = finv(~(unsigned)(key >> 32));   // exact score bits
            s_keep[r] = 1;
        } else {
            s_bx[r] = make_float4(0.f, 0.f, 0.f, 0.f);
            s_ar[r] = 0.f; s_sc[r] = -1.f; s_keep[r] = 0;
        }
    }

    // greedy NMS (matches the reference's sequential fori_loop exactly)
    for (int i = 0; i < nn - 1; i++) {
        __syncthreads();
        if (!s_keep[i]) continue;   // uniform across block
        float4 bi = s_bx[i];
        float  ai = s_ar[i];
        for (int j = i + 1 + tid; j < nn; j += nt) {
            if (!s_keep[j]) continue;
            float4 bj = s_bx[j];
            float w = fminf(bi.z, bj.z) - fmaxf(bi.x, bj.x);
            float h = fminf(bi.w, bj.w) - fmaxf(bi.y, bj.y);
            w = fmaxf(w, 0.f); h = fmaxf(h, 0.f);
            float inter = w * h;
            float iou = inter / (ai + s_ar[j] - inter);
            if (iou > IOUT) s_keep[j] = 0;
        }
    }
    __syncthreads();

    unsigned* ou  = g_u  + (size_t)b * CK + c * K;
    float4*   okb = g_kb + (size_t)b * CK + c * K;
    for (int r = tid; r < K; r += nt) {
        bool valid = (r < nn) && s_keep[r];
        ou[r]  = valid ? ~ford(s_sc[r]) : 0xFFFFFFFFu;  // ascending key, sentinel = invalid
        okb[r] = s_bx[r];
    }
}

// ============================================================
// Kernel 3: per image, exact top-200 via 4-pass radix select + small sort
// ============================================================
__global__ void topk_final_kernel(float* __restrict__ out) {
    int b = blockIdx.x, tid = threadIdx.x;
    const int nt = 1024;

    __shared__ unsigned hist[256];
    __shared__ unsigned s_prefix, s_rank, s_cless, s_ustar, s_V;
    __shared__ int s_done;
    __shared__ unsigned long long sel[256];
    __shared__ int eqbuf[256];
    __shared__ int s_n1, s_n2;

    const unsigned* up = g_u + (size_t)b * CK;

    if (tid == 0) {
        s_prefix = 0; s_rank = K; s_cless = 0; s_done = 0;
        s_ustar = 0xFFFFFFFFu; s_V = 0;
    }
    __syncthreads();

    // MSB-first radix select: find the K-th smallest key u (= K-th best score)
    for (int pass = 3; pass >= 0; pass--) {
        for (int i = tid; i < 256; i += nt) hist[i] = 0;
        __syncthreads();
        if (!s_done) {
            unsigned prefix = s_prefix;
            int shift = pass * 8;
            unsigned pmask = (pass == 3) ? 0u : (0xFFFFFFFFu << (shift + 8));
            for (int t = tid; t < CK; t += nt) {
                unsigned u = up[t];
                if (u != 0xFFFFFFFFu && (u & pmask) == prefix)
                    atomicAdd(&hist[(u >> shift) & 255u], 1u);
            }
        }
        __syncthreads();
        if (tid == 0 && !s_done) {
            if (pass == 3) {
                unsigned V = 0;
                for (int d = 0; d < 256; d++) V += hist[d];
                s_V = V;
                if (V <= (unsigned)K) s_done = 1;   // take all valid
            }
            if (!s_done) {
                int shift = pass * 8;
                unsigned r = s_rank, cum = 0; int d = 0;
                for (; d < 256; d++) { if (cum + hist[d] >= r) break; cum += hist[d]; }
                s_prefix |= (unsigned)d << shift;
                s_rank = r - cum;
                s_cless += cum;
                if (pass == 0) s_ustar = s_prefix;
            }
        }
        __syncthreads();
    }

    unsigned ustar = s_ustar, V = s_V;
    if (tid == 0) { s_n1 = 0; s_n2 = 0; }
    __syncthreads();

    // compact: strict winners + ties at the threshold
    for (int t = tid; t < CK; t += nt) {
        unsigned u = up[t];
        if (u == 0xFFFFFFFFu) continue;
        if (u < ustar) {
            int p = atomicAdd(&s_n1, 1);
            if (p < 256) sel[p] = ((unsigned long long)u << 32) | (unsigned)t;
        } else if (u == ustar && V > (unsigned)K) {
            int p = atomicAdd(&s_n2, 1);
            if (p < 256) eqbuf[p] = t;
        }
    }
    __syncthreads();

    int n1 = min(s_n1, 256), n2 = min(s_n2, 256);
    int total;
    if (V > (unsigned)K) {
        // ties broken by lowest index (top_k semantics): sort eqbuf, take first need
        for (int i = tid; i < 256; i += nt) if (i >= n2) eqbuf[i] = 0x7FFFFFFF;
        __syncthreads();
        for (int k = 2; k <= 256; k <<= 1) {
            for (int j = k >> 1; j > 0; j >>= 1) {
                for (int i = tid; i < 256; i += nt) {
                    int ixj = i ^ j;
                    if (ixj > i) {
                        bool up2 = ((i & k) == 0);
                        int a = eqbuf[i], d2 = eqbuf[ixj];
                        if ((a > d2) == up2) { eqbuf[i] = d2; eqbuf[ixj] = a; }
                    }
                }
                __syncthreads();
            }
        }
        int need = K - n1;   // n1 == count(u < ustar) < K
        if (tid < need)
            sel[n1 + tid] = ((unsigned long long)ustar << 32) | (unsigned)eqbuf[tid];
        total = K;
    } else {
        total = n1;          // == V
    }
    __syncthreads();

    for (int i = tid; i < 256; i += nt) if (i >= total) sel[i] = 0xFFFFFFFFFFFFFFFFULL;
    __syncthreads();

    // sort the <=200 selected by (score desc, idx asc)
    for (int k = 2; k <= 256; k <<= 1) {
        for (int j = k >> 1; j > 0; j >>= 1) {
            for (int i = tid; i < 256; i += nt) {
                int ixj = i ^ j;
                if (ixj > i) {
                    bool up2 = ((i & k) == 0);
                    unsigned long long a = sel[i], d2 = sel[ixj];
                    if ((a > d2) == up2) { sel[i] = d2; sel[ixj] = a; }
                }
            }
            __syncthreads();
        }
    }

    // outputs concatenated: fb[B][K][4], fl[B][K], fs[B][K]
    float* fb = out;
    float* fl = out + (size_t)BATCH * K * 4;
    float* fs = fl + (size_t)BATCH * K;

    for (int r = tid; r < K; r += nt) {
        float4 bx = make_float4(0.f, 0.f, 0.f, 0.f);
        float scv = 0.f; int lab = 0;
        if (r < total) {
            unsigned long long key = sel[r];
            unsigned t = (unsigned)(key & 0xFFFFFFFFu);
            unsigned u = (unsigned)(key >> 32);
            scv = finv(~u);            // exact score bits
            lab = (int)(t / K) + 1;
            bx  = g_kb[(size_t)b * CK + t];
        }
        size_t base = ((size_t)b * K + r) * 4;
        fb[base + 0] = bx.x; fb[base + 1] = bx.y;
        fb[base + 2] = bx.z; fb[base + 3] = bx.w;
        fl[(size_t)b * K + r] = (float)lab;
        fs[(size_t)b * K + r] = scv;
    }
}

// ============================================================
extern "C" void kernel_launch(void* const* d_in, const int* in_sizes, int n_in,
                              void* d_out, int out_size) {
    const float*  bb  = (const float*)d_in[0];   // (32, 4, 15130)
    const float*  sc  = (const float*)d_in[1];   // (32, 81, 15130)
    const float*  sxy = (const float*)d_in[2];   // (1,)
    const float*  swh = (const float*)d_in[3];   // (1,)
    const float4* db  = (const float4*)d_in[4];  // (1, 15130, 4)

    init_kernel<<<(BATCH * C + 1023) / 1024, 1024>>>();
    dim3 g1((N_ANCH + 127) / 128, BATCH);
    decode_kernel<<<g1, 128>>>(bb, sc, sxy, swh, db);
    nms_kernel<<<dim3(C, BATCH), 256>>>();
    topk_final_kernel<<<BATCH, 1024>>>((float*)d_out);
}

// round 10
// speedup vs baseline: 1.1379x; 1.1379x over previous
#include <cuda_runtime.h>
#include <math.h>

#define N_ANCH 15130
#define BATCH  32
#define NCLS   81
#define C      80      // foreground classes (1..80)
#define K      200
#define CK     (C * K) // 16000
#define CONF   0.05f
#define IOUT   0.5f
#define CAP2   2048    // per-class candidate capacity (mean ~434, sd ~20)
#define TB1    128     // decode tile width (anchors per block)

// ---- scratch (device globals; zero-initialized at module load) ----
__device__ float4             g_boxes[BATCH * N_ANCH];          // decoded ltrb
__device__ unsigned long long g_cand[(size_t)BATCH * C * CAP2]; // (~ord(score)<<32)|anchor
__device__ int                g_cnt[BATCH * C];                 // per (b,c) count; re-zeroed by topk each launch
__device__ unsigned           g_u[BATCH * CK];                  // kept keys: ~ord(score), 0xFFFFFFFF = invalid
__device__ float4             g_kb[BATCH * CK];                 // per-class top-k boxes

// monotonic float->uint order map (ascending) and exact inverse
__device__ __forceinline__ unsigned ford(float f) {
    unsigned u = __float_as_uint(f);
    return (u & 0x80000000u) ? ~u : (u | 0x80000000u);
}
__device__ __forceinline__ float finv(unsigned v) {
    unsigned b = (v & 0x80000000u) ? (v & 0x7FFFFFFFu) : ~v;
    return __uint_as_float(b);
}

// ============================================================
// Kernel 1: box decode + softmax (smem-staged) + warp-aggregated emission
// ============================================================
__global__ void __launch_bounds__(TB1) decode_kernel(
        const float* __restrict__ bb, const float* __restrict__ sc,
        const float* __restrict__ sxy_p, const float* __restrict__ swh_p,
        const float4* __restrict__ db) {
    __shared__ float s_e[NCLS * TB1];   // [class][anchor-in-tile]; private column per thread
    int tid = threadIdx.x, lane = tid & 31;
    int n0 = blockIdx.x * TB1;
    int b  = blockIdx.y;
    int n  = n0 + tid;
    bool act = n < N_ANCH;
    unsigned amask = __ballot_sync(0xFFFFFFFFu, act);

    // coalesced tile load: 81 rows x 128 anchors
    {
        const float* base = sc + (size_t)b * NCLS * N_ANCH + n0;
        int lim = N_ANCH - n0;
#pragma unroll 27
        for (int cc = 0; cc < NCLS; cc++)
            s_e[cc * TB1 + tid] = (tid < lim) ? base[(size_t)cc * N_ANCH + tid] : 0.f;
    }

    float sxy = sxy_p[0], swh = swh_p[0];
    if (act) {
        float4 d = db[n];
        const float* bp = bb + (size_t)b * 4 * N_ANCH + n;
        float x = bp[0]              * sxy * d.z + d.x;
        float y = bp[N_ANCH]         * sxy * d.w + d.y;
        float w = expf(bp[2 * N_ANCH] * swh) * d.z;
        float h = expf(bp[3 * N_ANCH] * swh) * d.w;
        g_boxes[(size_t)b * N_ANCH + n] =
            make_float4(x - 0.5f * w, y - 0.5f * h, x + 0.5f * w, y + 0.5f * h);
    }
    if (!act) return;   // no block-wide syncs below; smem columns are thread-private

    float m = s_e[tid];
    for (int cc = 1; cc < NCLS; cc++) m = fmaxf(m, s_e[cc * TB1 + tid]);
    float sum = 0.f;
    for (int cc = 0; cc < NCLS; cc++) {
        float e = expf(s_e[cc * TB1 + tid] - m);
        sum += e;
        s_e[cc * TB1 + tid] = e;
    }
    float inv = 1.0f / sum;

    // emit candidates: one atomic per warp per passing class
    for (int cc = 1; cc < NCLS; cc++) {
        float p = s_e[cc * TB1 + tid] * inv;
        bool pass = p > CONF;
        unsigned m2 = __ballot_sync(amask, pass);
        if (m2) {
            int cell = b * C + (cc - 1);
            int ldr = __ffs(m2) - 1;
            int base = 0;
            if (lane == ldr) base = atomicAdd(&g_cnt[cell], __popc(m2));
            base = __shfl_sync(amask, base, ldr);
            if (pass) {
                int p2 = base + __popc(m2 & ((1u << lane) - 1));
                if (p2 < CAP2)
                    g_cand[(size_t)cell * CAP2 + p2] =
                        ((unsigned long long)(~ford(p)) << 32) | (unsigned)n;
            }
        }
    }
}

// ============================================================
// Kernel 2: per (batch,class): sort candidates -> bitmask NMS
// ============================================================
__global__ void __launch_bounds__(256) nms_kernel() {
    int c = blockIdx.x, b = blockIdx.y;
    int tid = threadIdx.x; const int nt = 256;
    int lane = tid & 31, wd = tid >> 5;
    int cell = b * C + c;

    __shared__ unsigned long long keys[CAP2];     // 16 KB
    __shared__ float4 s_bx[K];
    __shared__ float  s_ar[K];
    __shared__ unsigned long long s_mat[K * 4];   // suppression bitmask rows
    __shared__ unsigned long long s_kp[4];        // keep bits

    int cnt = min(g_cnt[cell], CAP2);
    int m = 256;
    while (m < cnt) m <<= 1;   // <= CAP2

    const unsigned long long* cand = g_cand + (size_t)cell * CAP2;
    for (int i = tid; i < m; i += nt)
        keys[i] = (i < cnt) ? cand[i] : 0xFFFFFFFFFFFFFFFFULL;
    for (int i = tid; i < K * 4; i += nt) s_mat[i] = 0ull;
    __syncthreads();

    // bitonic sort ascending on (~ord(score), idx) => score desc, idx asc
    for (int k = 2; k <= m; k <<= 1) {
        for (int j = k >> 1; j > 0; j >>= 1) {
            for (int i = tid; i < m; i += nt) {
                int ixj = i ^ j;
                if (ixj > i) {
                    bool up = ((i & k) == 0);
                    unsigned long long a = keys[i], d2 = keys[ixj];
                    if ((a > d2) == up) { keys[i] = d2; keys[ixj] = a; }
                }
            }
            __syncthreads();
        }
    }

    int nn = min(cnt, K);
    if (tid < K) {
        if (tid < nn) {
            unsigned idx = (unsigned)(keys[tid] & 0xFFFFFFFFu);
            float4 bx = g_boxes[(size_t)b * N_ANCH + idx];
            s_bx[tid] = bx;
            s_ar[tid] = (bx.z - bx.x) * (bx.w - bx.y);
        } else {
            s_bx[tid] = make_float4(0.f, 0.f, 0.f, 0.f);
            s_ar[tid] = 0.f;
        }
    }
    __syncthreads();

    // parallel IoU suppression matrix: warp per row (i), lanes over j
    for (int i = wd; i < nn; i += 8) {
        float4 bi = s_bx[i]; float ai = s_ar[i];
        for (int j = i + 1 + lane; j < nn; j += 32) {
            float4 bj = s_bx[j];
            float w = fminf(bi.z, bj.z) - fmaxf(bi.x, bj.x);
            float h = fminf(bi.w, bj.w) - fmaxf(bi.y, bj.y);
            w = fmaxf(w, 0.f); h = fmaxf(h, 0.f);
            float inter = w * h;
            float iou = inter / (ai + s_ar[j] - inter);
            if (iou > IOUT)
                atomicOr(&s_mat[i * 4 + (j >> 6)], 1ull << (j & 63));
        }
    }
    __syncthreads();

    // serial greedy resolve on one thread (exactly matches reference fori_loop)
    if (tid == 0) {
        unsigned long long r0 = 0, r1 = 0, r2 = 0, r3 = 0;
        unsigned long long k0 = 0, k1 = 0, k2 = 0, k3 = 0;
#define RESOLVE(W, RW, KW)                                              \
        for (int ib = 0; ib < 64; ib++) {                               \
            int i = (W) * 64 + ib;                                      \
            if (i >= nn) break;                                         \
            if (!((RW >> ib) & 1ull)) {                                 \
                KW |= 1ull << ib;                                       \
                r0 |= s_mat[i * 4 + 0]; r1 |= s_mat[i * 4 + 1];         \
                r2 |= s_mat[i * 4 + 2]; r3 |= s_mat[i * 4 + 3];         \
            }                                                           \
        }
        RESOLVE(0, r0, k0) RESOLVE(1, r1, k1) RESOLVE(2, r2, k2) RESOLVE(3, r3, k3)
#undef RESOLVE
        s_kp[0] = k0; s_kp[1] = k1; s_kp[2] = k2; s_kp[3] = k3;
    }
    __syncthreads();

    unsigned* ou  = g_u  + (size_t)b * CK + c * K;
    float4*   okb = g_kb + (size_t)b * CK + c * K;
    if (tid < K) {
        bool valid = (tid < nn) && ((s_kp[tid >> 6] >> (tid & 63)) & 1ull);
        ou[tid]  = valid ? (unsigned)(keys[tid] >> 32) : 0xFFFFFFFFu;
        okb[tid] = s_bx[tid];
    }
}

// ============================================================
// Kernel 3: per image, exact top-200 via radix select (parallel scans)
// ============================================================
__global__ void __launch_bounds__(1024) topk_final_kernel(float* __restrict__ out) {
    const int nt = 1024;
    int b = blockIdx.x, tid = threadIdx.x;
    int lane = tid & 31, wid = tid >> 5;

    __shared__ unsigned hist[256];
    __shared__ unsigned cum[256];
    __shared__ unsigned wsum[8];
    __shared__ unsigned s_prefix, s_rank, s_ustar, s_V;
    __shared__ int s_done, s_n1, s_n2;
    __shared__ unsigned long long sel[256];
    __shared__ int eqbuf[256];

    const unsigned* up = g_u + (size_t)b * CK;

    if (tid == 0) { s_prefix = 0; s_rank = K; s_done = 0; s_ustar = 0xFFFFFFFFu; s_V = 0; }
    __syncthreads();

    for (int pass = 3; pass >= 0; pass--) {
        for (int i = tid; i < 256; i += nt) hist[i] = 0;
        __syncthreads();
        int done = s_done;
        unsigned prefix = s_prefix;
        int shift = pass * 8;
        unsigned pmask = (pass == 3) ? 0u : (0xFFFFFFFFu << (shift + 8));

        if (!done) {
            for (int t0 = 0; t0 < CK; t0 += nt) {
                int t = t0 + tid;
                unsigned bin = 0xFFFFFFFFu;
                if (t < CK) {
                    unsigned u = up[t];
                    if (u != 0xFFFFFFFFu && (u & pmask) == prefix)
                        bin = (u >> shift) & 255u;
                }
                unsigned peers = __match_any_sync(0xFFFFFFFFu, bin);
                if (bin != 0xFFFFFFFFu && lane == (__ffs(peers) - 1))
                    atomicAdd(&hist[bin], (unsigned)__popc(peers));
            }
        }
        __syncthreads();

        // parallel inclusive prefix over 256 bins
        unsigned x = 0;
        if (tid < 256) {
            x = hist[tid];
            for (int o = 1; o < 32; o <<= 1) {
                unsigned y = __shfl_up_sync(0xFFFFFFFFu, x, o);
                if (lane >= o) x += y;
            }
            if (lane == 31) wsum[wid] = x;
        }
        __syncthreads();
        if (tid < 256) {
            unsigned off = 0;
            for (int w = 0; w < wid; w++) off += wsum[w];
            cum[tid] = x + off;
        }
        __syncthreads();

        if (pass == 3 && tid == 0 && !done) {
            s_V = cum[255];
            if (cum[255] <= (unsigned)K) s_done = 1;   // take all valid
        }
        __syncthreads();
        done = s_done;
        unsigned r = s_rank;
        __syncthreads();   // snapshot rank before winner updates
        if (!done && tid < 256) {
            unsigned prev = tid ? cum[tid - 1] : 0u;
            if (prev < r && cum[tid] >= r) {   // exactly one winner
                unsigned np = prefix | ((unsigned)tid << shift);
                s_prefix = np;
                s_rank = r - prev;
                if (pass == 0) s_ustar = np;
            }
        }
        __syncthreads();
    }

    if (tid == 0) { s_n1 = 0; s_n2 = 0; }
    __syncthreads();
    int done = s_done;
    unsigned ustar = s_ustar;

    // compact strict winners (+ ties at threshold), warp-aggregated
    for (int t0 = 0; t0 < CK; t0 += nt) {
        int t = t0 + tid;
        unsigned u = (t < CK) ? up[t] : 0xFFFFFFFFu;
        bool w1 = (u != 0xFFFFFFFFu) && (done || (u < ustar));
        unsigned m1 = __ballot_sync(0xFFFFFFFFu, w1);
        if (w1) {
            int ldr = __ffs(m1) - 1;
            int base = 0;
            if (lane == ldr) base = atomicAdd(&s_n1, __popc(m1));
            base = __shfl_sync(m1, base, ldr);
            int p = base + __popc(m1 & ((1u << lane) - 1));
            if (p < 256) sel[p] = ((unsigned long long)u << 32) | (unsigned)t;
        }
        bool w2 = (!done) && (u == ustar);
        unsigned m2 = __ballot_sync(0xFFFFFFFFu, w2);
        if (w2) {
            int ldr = __ffs(m2) - 1;
            int base = 0;
            if (lane == ldr) base = atomicAdd(&s_n2, __popc(m2));
            base = __shfl_sync(m2, base, ldr);
            int p = base + __popc(m2 & ((1u << lane) - 1));
            if (p < 256) eqbuf[p] = t;
        }
    }
    __syncthreads();
    int n1 = min(s_n1, 256), n2 = min(s_n2, 256);
    int total;
    if (!done) {
        // resolve ties by lowest index (top_k semantics)
        for (int i = tid; i < 256; i += nt) if (i >= n2) eqbuf[i] = 0x7FFFFFFF;
        __syncthreads();
        for (int k = 2; k <= 256; k <<= 1) {
            for (int j = k >> 1; j > 0; j >>= 1) {
                for (int i = tid; i < 256; i += nt) {
                    int ixj = i ^ j;
                    if (ixj > i) {
                        bool up2 = ((i & k) == 0);
                        int a = eqbuf[i], d2 = eqbuf[ixj];
                        if ((a > d2) == up2) { eqbuf[i] = d2; eqbuf[ixj] = a; }
                    }
                }
                __syncthreads();
            }
        }
        int need = K - n1;
        if (tid < need)
            sel[n1 + tid] = ((unsigned long long)ustar << 32) | (unsigned)eqbuf[tid];
        total = K;
    } else {
        total = n1;   // == V <= K
    }
    __syncthreads();
    for (int i = tid; i < 256; i += nt) if (i >= total) sel[i] = 0xFFFFFFFFFFFFFFFFULL;
    __syncthreads();

    // final sort of <=200 selected: (score desc, idx asc)
    for (int k = 2; k <= 256; k <<= 1) {
        for (int j = k >> 1; j > 0; j >>= 1) {
            for (int i = tid; i < 256; i += nt) {
                int ixj = i ^ j;
                if (ixj > i) {
                    bool up2 = ((i & k) == 0);
                    unsigned long long a = sel[i], d2 = sel[ixj];
                    if ((a > d2) == up2) { sel[i] = d2; sel[ixj] = a; }
                }
            }
            __syncthreads();
        }
    }

    // outputs concatenated: fb[B][K][4], fl[B][K], fs[B][K]
    float* fb = out;
    float* fl = out + (size_t)BATCH * K * 4;
    float* fs = fl + (size_t)BATCH * K;

    for (int r = tid; r < K; r += nt) {
        float4 bx = make_float4(0.f, 0.f, 0.f, 0.f);
        float scv = 0.f; int lab = 0;
        if (r < total) {
            unsigned long long key = sel[r];
            unsigned t = (unsigned)(key & 0xFFFFFFFFu);
            unsigned u = (unsigned)(key >> 32);
            scv = finv(~u);           // exact score bits
            lab = (int)(t / K) + 1;
            bx  = g_kb[(size_t)b * CK + t];
        }
        size_t base = ((size_t)b * K + r) * 4;
        fb[base + 0] = bx.x; fb[base + 1] = bx.y;
        fb[base + 2] = bx.z; fb[base + 3] = bx.w;
        fl[(size_t)b * K + r] = (float)lab;
        fs[(size_t)b * K + r] = scv;
    }

    // reset per-class counters for the next graph replay (replaces init kernel;
    // first-ever call sees zero-initialized device globals)
    for (int i = tid; i < C; i += nt) g_cnt[b * C + i] = 0;
}

// ============================================================
extern "C" void kernel_launch(void* const* d_in, const int* in_sizes, int n_in,
                              void* d_out, int out_size) {
    const float*  bb  = (const float*)d_in[0];   // (32, 4, 15130)
    const float*  sc  = (const float*)d_in[1];   // (32, 81, 15130)
    const float*  sxy = (const float*)d_in[2];   // (1,)
    const float*  swh = (const float*)d_in[3];   // (1,)
    const float4* db  = (const float4*)d_in[4];  // (1, 15130, 4)

    dim3 g1((N_ANCH + TB1 - 1) / TB1, BATCH);
    decode_kernel<<<g1, TB1>>>(bb, sc, sxy, swh, db);
    nms_kernel<<<dim3(C, BATCH), 256>>>();
    topk_final_kernel<<<BATCH, 1024>>>((float*)d_out);
}

// round 11
// speedup vs baseline: 1.4807x; 1.3012x over previous
#include <cuda_runtime.h>
#include <math.h>

#define N_ANCH 15130
#define BATCH  32
#define NCLS   81
#define C      80      // foreground classes (1..80)
#define K      200
#define CK     (C * K) // 16000
#define CONF   0.05f
#define IOUT   0.5f
#define CAP2   1024    // per-class candidate capacity (counts ~434 +/- 20 -> 29 sigma)

// ---- scratch (device globals; zero-initialized at module load) ----
__device__ float4             g_boxes[BATCH * N_ANCH];          // decoded ltrb
__device__ unsigned long long g_cand[(size_t)BATCH * C * CAP2]; // (~ord(score)<<32)|anchor
__device__ int                g_cnt[BATCH * C];                 // per (b,c) count; re-zeroed by topk each launch
__device__ unsigned           g_u[BATCH * CK];                  // kept keys: ~ord(score), 0xFFFFFFFF = invalid
__device__ float4             g_kb[BATCH * CK];                 // per-class top-k boxes

// monotonic float->uint order map (ascending) and exact inverse
__device__ __forceinline__ unsigned ford(float f) {
    unsigned u = __float_as_uint(f);
    return (u & 0x80000000u) ? ~u : (u | 0x80000000u);
}
__device__ __forceinline__ float finv(unsigned v) {
    unsigned b = (v & 0x80000000u) ? (v & 0x7FFFFFFFu) : ~v;
    return __uint_as_float(b);
}

// ============================================================
// Kernel 1: box decode + softmax via 3 streaming passes (no smem)
//   pass1 (DRAM): running max     pass2 (L2): exp-sum in class order
//   pass3 (L2):   logit-space prefilter, exact p only for survivors
// Candidate keys are bit-identical to the smem-staged version.
// ============================================================
__global__ void __launch_bounds__(256) decode_kernel(
        const float* __restrict__ bb, const float* __restrict__ sc,
        const float* __restrict__ sxy_p, const float* __restrict__ swh_p,
        const float4* __restrict__ db) {
    int n = blockIdx.x * 256 + threadIdx.x;
    int b = blockIdx.y;
    if (n >= N_ANCH) return;   // no block syncs anywhere below

    // box decode (precise expf, matches reference)
    {
        float sxy = sxy_p[0], swh = swh_p[0];
        float4 d = db[n];
        const float* bp = bb + (size_t)b * 4 * N_ANCH + n;
        float x = bp[0]              * sxy * d.z + d.x;
        float y = bp[N_ANCH]         * sxy * d.w + d.y;
        float w = expf(bp[2 * N_ANCH] * swh) * d.z;
        float h = expf(bp[3 * N_ANCH] * swh) * d.w;
        g_boxes[(size_t)b * N_ANCH + n] =
            make_float4(x - 0.5f * w, y - 0.5f * h, x + 0.5f * w, y + 0.5f * h);
    }

    const float* sp = sc + (size_t)b * NCLS * N_ANCH + n;

    // pass 1: max over 81 classes (pure stream)
    float m = sp[0];
#pragma unroll 16
    for (int cc = 1; cc < NCLS; cc++)
        m = fmaxf(m, sp[(size_t)cc * N_ANCH]);

    // pass 2: sum of exp(v - m) in class order (L2-hot re-read)
    float s = 0.f;
#pragma unroll 4
    for (int cc = 0; cc < NCLS; cc++)
        s += expf(sp[(size_t)cc * N_ANCH] - m);
    float inv = 1.0f / s;
    // loose logit-space threshold: admits everything that could pass p > CONF
    float thresh = m + logf(CONF * s) - 1e-4f;

    // pass 3: emit candidates (exact test only for the rare survivors)
#pragma unroll 4
    for (int cc = 1; cc < NCLS; cc++) {
        float v = sp[(size_t)cc * N_ANCH];
        if (v > thresh) {
            float p = expf(v - m) * inv;   // exact score bits
            if (p > CONF) {
                int cell = b * C + (cc - 1);
                int pos = atomicAdd(&g_cnt[cell], 1);
                if (pos < CAP2)
                    g_cand[(size_t)cell * CAP2 + pos] =
                        ((unsigned long long)(~ford(p)) << 32) | (unsigned)n;
            }
        }
    }
}

// ============================================================
// Kernel 2: per (batch,class): radix-select top-200 -> sort 256 -> bitmask NMS
// ============================================================
__global__ void __launch_bounds__(256) nms_kernel() {
    int c = blockIdx.x, b = blockIdx.y;
    int tid = threadIdx.x; const int nt = 256;
    int lane = tid & 31, wd = tid >> 5;
    int cell = b * C + c;

    __shared__ unsigned long long keys[CAP2];     // 8 KB
    __shared__ unsigned hist[256];
    __shared__ unsigned wsum[8];
    __shared__ unsigned s_prefix, s_rank;
    __shared__ int s_nsel;
    __shared__ unsigned long long sel[256];
    __shared__ float4 s_bx[K];
    __shared__ float  s_ar[K];
    __shared__ unsigned long long s_mat[K * 4];   // suppression bitmask rows
    __shared__ unsigned long long s_kp[4];        // keep bits

    int cnt = min(g_cnt[cell], CAP2);

    const unsigned long long* cand = g_cand + (size_t)cell * CAP2;
    for (int i = tid; i < cnt; i += nt) keys[i] = cand[i];
    for (int i = tid; i < K * 4; i += nt) s_mat[i] = 0ull;
    if (tid == 0) { s_prefix = 0; s_rank = K; s_nsel = 0; }
    __syncthreads();

    int nsel;
    if (cnt > 256) {
        // radix select: smallest u (upper 32 of key) with count(<=u) >= K
        for (int pass = 3; pass >= 0; pass--) {
            hist[tid] = 0;
            __syncthreads();
            unsigned prefix = s_prefix;
            int shift = pass * 8;
            unsigned pmask = (pass == 3) ? 0u : (0xFFFFFFFFu << (shift + 8));
            for (int i = tid; i < cnt; i += nt) {
                unsigned u = (unsigned)(keys[i] >> 32);
                if ((u & pmask) == prefix)
                    atomicAdd(&hist[(u >> shift) & 255u], 1u);
            }
            __syncthreads();
            // inclusive prefix over 256 bins
            unsigned x = hist[tid];
            for (int o = 1; o < 32; o <<= 1) {
                unsigned y = __shfl_up_sync(0xFFFFFFFFu, x, o);
                if (lane >= o) x += y;
            }
            if (lane == 31) wsum[wd] = x;
            __syncthreads();
            unsigned off = 0;
            for (int w = 0; w < wd; w++) off += wsum[w];
            unsigned cum = x + off;
            hist[tid] = cum;
            __syncthreads();
            unsigned r = s_rank;
            __syncthreads();   // snapshot rank before winner update
            unsigned prev = tid ? hist[tid - 1] : 0u;
            if (prev < r && cum >= r) {    // exactly one winner
                s_prefix = prefix | ((unsigned)tid << shift);
                s_rank = r - prev;
            }
            __syncthreads();
        }
        unsigned ustar = s_prefix;

        // compact: strict (u < ustar, provably < K of them), then ties (u == ustar)
        for (int i = tid; i < cnt; i += nt) {
            unsigned long long k = keys[i];
            if ((unsigned)(k >> 32) < ustar) {
                int p = atomicAdd(&s_nsel, 1);
                sel[p] = k;                // p < K always
            }
        }
        __syncthreads();
        for (int i = tid; i < cnt; i += nt) {
            unsigned long long k = keys[i];
            if ((unsigned)(k >> 32) == ustar) {
                int p = atomicAdd(&s_nsel, 1);
                if (p < 256) sel[p] = k;
            }
        }
        __syncthreads();
        nsel = min(s_nsel, 256);
    } else {
        for (int i = tid; i < cnt; i += nt) sel[i] = keys[i];
        __syncthreads();
        nsel = cnt;
    }

    if (tid >= nsel) sel[tid] = 0xFFFFFFFFFFFFFFFFULL;  // pad
    __syncthreads();

    // bitonic sort 256 ascending on (~ord(score), idx) => score desc, idx asc
    for (int k = 2; k <= 256; k <<= 1) {
        for (int j = k >> 1; j > 0; j >>= 1) {
            int ixj = tid ^ j;
            if (ixj > tid) {
                bool up = ((tid & k) == 0);
                unsigned long long a = sel[tid], d2 = sel[ixj];
                if ((a > d2) == up) { sel[tid] = d2; sel[ixj] = a; }
            }
            __syncthreads();
        }
    }

    int nn = min(nsel, K);
    if (tid < K) {
        if (tid < nn) {
            unsigned idx = (unsigned)(sel[tid] & 0xFFFFFFFFu);
            float4 bx = g_boxes[(size_t)b * N_ANCH + idx];
            s_bx[tid] = bx;
            s_ar[tid] = (bx.z - bx.x) * (bx.w - bx.y);
        } else {
            s_bx[tid] = make_float4(0.f, 0.f, 0.f, 0.f);
            s_ar[tid] = 0.f;
        }
    }
    __syncthreads();

    // parallel IoU suppression matrix: warp per row (i), lanes over j
    for (int i = wd; i < nn; i += 8) {
        float4 bi = s_bx[i]; float ai = s_ar[i];
        for (int j = i + 1 + lane; j < nn; j += 32) {
            float4 bj = s_bx[j];
            float w = fminf(bi.z, bj.z) - fmaxf(bi.x, bj.x);
            float h = fminf(bi.w, bj.w) - fmaxf(bi.y, bj.y);
            w = fmaxf(w, 0.f); h = fmaxf(h, 0.f);
            float inter = w * h;
            float iou = inter / (ai + s_ar[j] - inter);
            if (iou > IOUT)
                atomicOr(&s_mat[i * 4 + (j >> 6)], 1ull << (j & 63));
        }
    }
    __syncthreads();

    // serial greedy resolve on one thread (exactly matches reference fori_loop)
    if (tid == 0) {
        unsigned long long r0 = 0, r1 = 0, r2 = 0, r3 = 0;
        unsigned long long k0 = 0, k1 = 0, k2 = 0, k3 = 0;
#define RESOLVE(W, RW, KW)                                              \
        for (int ib = 0; ib < 64; ib++) {                               \
            int i = (W) * 64 + ib;                                      \
            if (i >= nn) break;                                         \
            if (!((RW >> ib) & 1ull)) {                                 \
                KW |= 1ull << ib;                                       \
                r0 |= s_mat[i * 4 + 0]; r1 |= s_mat[i * 4 + 1];         \
                r2 |= s_mat[i * 4 + 2]; r3 |= s_mat[i * 4 + 3];         \
            }                                                           \
        }
        RESOLVE(0, r0, k0) RESOLVE(1, r1, k1) RESOLVE(2, r2, k2) RESOLVE(3, r3, k3)
#undef RESOLVE
        s_kp[0] = k0; s_kp[1] = k1; s_kp[2] = k2; s_kp[3] = k3;
    }
    __syncthreads();

    unsigned* ou  = g_u  + (size_t)b * CK + c * K;
    float4*   okb = g_kb + (size_t)b * CK + c * K;
    if (tid < K) {
        bool valid = (tid < nn) && ((s_kp[tid >> 6] >> (tid & 63)) & 1ull);
        ou[tid]  = valid ? (unsigned)(sel[tid] >> 32) : 0xFFFFFFFFu;
        okb[tid] = s_bx[tid];
    }
}

// ============================================================
// Kernel 3: per image, exact top-200 via radix select (parallel scans)
// ============================================================
__global__ void __launch_bounds__(512) topk_final_kernel(float* __restrict__ out) {
    const int nt = 512;
    int b = blockIdx.x, tid = threadIdx.x;
    int lane = tid & 31, wid = tid >> 5;

    __shared__ unsigned hist[256];
    __shared__ unsigned cum[256];
    __shared__ unsigned wsum[8];
    __shared__ unsigned s_prefix, s_rank, s_ustar, s_V;
    __shared__ int s_done, s_n1, s_n2;
    __shared__ unsigned long long sel[256];
    __shared__ int eqbuf[256];

    const unsigned* up = g_u + (size_t)b * CK;

    if (tid == 0) { s_prefix = 0; s_rank = K; s_done = 0; s_ustar = 0xFFFFFFFFu; s_V = 0; }
    __syncthreads();

    for (int pass = 3; pass >= 0; pass--) {
        for (int i = tid; i < 256; i += nt) hist[i] = 0;
        __syncthreads();
        int done = s_done;
        unsigned prefix = s_prefix;
        int shift = pass * 8;
        unsigned pmask = (pass == 3) ? 0u : (0xFFFFFFFFu << (shift + 8));

        if (!done) {
            for (int t0 = 0; t0 < CK; t0 += nt) {
                int t = t0 + tid;
                unsigned bin = 0xFFFFFFFFu;
                if (t < CK) {
                    unsigned u = up[t];
                    if (u != 0xFFFFFFFFu && (u & pmask) == prefix)
                        bin = (u >> shift) & 255u;
                }
                unsigned peers = __match_any_sync(0xFFFFFFFFu, bin);
                if (bin != 0xFFFFFFFFu && lane == (__ffs(peers) - 1))
                    atomicAdd(&hist[bin], (unsigned)__popc(peers));
            }
        }
        __syncthreads();

        // parallel inclusive prefix over 256 bins
        unsigned x = 0;
        if (tid < 256) {
            x = hist[tid];
            for (int o = 1; o < 32; o <<= 1) {
                unsigned y = __shfl_up_sync(0xFFFFFFFFu, x, o);
                if (lane >= o) x += y;
            }
            if (lane == 31) wsum[wid] = x;
        }
        __syncthreads();
        if (tid < 256) {
            unsigned off = 0;
            for (int w = 0; w < wid; w++) off += wsum[w];
            cum[tid] = x + off;
        }
        __syncthreads();

        if (pass == 3 && tid == 0 && !done) {
            s_V = cum[255];
            if (cum[255] <= (unsigned)K) s_done = 1;   // take all valid
        }
        __syncthreads();
        done = s_done;
        unsigned r = s_rank;
        __syncthreads();   // snapshot rank before winner updates
        if (!done && tid < 256) {
            unsigned prev = tid ? cum[tid - 1] : 0u;
            if (prev < r && cum[tid] >= r) {   // exactly one winner
                unsigned np = prefix | ((unsigned)tid << shift);
                s_prefix = np;
                s_rank = r - prev;
                if (pass == 0) s_ustar = np;
            }
        }
        __syncthreads();
    }

    if (tid == 0) { s_n1 = 0; s_n2 = 0; }
    __syncthreads();
    int done = s_done;
    unsigned ustar = s_ustar;

    // compact strict winners (+ ties at threshold), warp-aggregated
    for (int t0 = 0; t0 < CK; t0 += nt) {
        int t = t0 + tid;
        unsigned u = (t < CK) ? up[t] : 0xFFFFFFFFu;
        bool w1 = (u != 0xFFFFFFFFu) && (done || (u < ustar));
        unsigned m1 = __ballot_sync(0xFFFFFFFFu, w1);
        if (w1) {
            int ldr = __ffs(m1) - 1;
            int base = 0;
            if (lane == ldr) base = atomicAdd(&s_n1, __popc(m1));
            base = __shfl_sync(m1, base, ldr);
            int p = base + __popc(m1 & ((1u << lane) - 1));
            if (p < 256) sel[p] = ((unsigned long long)u << 32) | (unsigned)t;
        }
        bool w2 = (!done) && (u == ustar);
        unsigned m2 = __ballot_sync(0xFFFFFFFFu, w2);
        if (w2) {
            int ldr = __ffs(m2) - 1;
            int base = 0;
            if (lane == ldr) base = atomicAdd(&s_n2, __popc(m2));
            base = __shfl_sync(m2, base, ldr);
            int p = base + __popc(m2 & ((1u << lane) - 1));
            if (p < 256) eqbuf[p] = t;
        }
    }
    __syncthreads();
    int n1 = min(s_n1, 256), n2 = min(s_n2, 256);
    int total;
    if (!done) {
        // resolve ties by lowest index (top_k semantics)
        for (int i = tid; i < 256; i += nt) if (i >= n2) eqbuf[i] = 0x7FFFFFFF;
        __syncthreads();
        for (int k = 2; k <= 256; k <<= 1) {
            for (int j = k >> 1; j > 0; j >>= 1) {
                for (int i = tid; i < 256; i += nt) {
                    int ixj = i ^ j;
                    if (ixj > i) {
                        bool up2 = ((i & k) == 0);
                        int a = eqbuf[i], d2 = eqbuf[ixj];
                        if ((a > d2) == up2) { eqbuf[i] = d2; eqbuf[ixj] = a; }
                    }
                }
                __syncthreads();
            }
        }
        int need = K - n1;
        if (tid < need)
            sel[n1 + tid] = ((unsigned long long)ustar << 32) | (unsigned)eqbuf[tid];
        total = K;
    } else {
        total = n1;   // == V <= K
    }
    __syncthreads();
    for (int i = tid; i < 256; i += nt) if (i >= total) sel[i] = 0xFFFFFFFFFFFFFFFFULL;
    __syncthreads();

    // final sort of <=200 selected: (score desc, idx asc)
    for (int k = 2; k <= 256; k <<= 1) {
        for (int j = k >> 1; j > 0; j >>= 1) {
            for (int i = tid; i < 256; i += nt) {
                int ixj = i ^ j;
                if (ixj > i) {
                    bool up2 = ((i & k) == 0);
                    unsigned long long a = sel[i], d2 = sel[ixj];
                    if ((a > d2) == up2) { sel[i] = d2; sel[ixj] = a; }
                }
            }
            __syncthreads();
        }
    }

    // outputs concatenated: fb[B][K][4], fl[B][K], fs[B][K]
    float* fb = out;
    float* fl = out + (size_t)BATCH * K * 4;
    float* fs = fl + (size_t)BATCH * K;

    for (int r = tid; r < K; r += nt) {
        float4 bx = make_float4(0.f, 0.f, 0.f, 0.f);
        float scv = 0.f; int lab = 0;
        if (r < total) {
            unsigned long long key = sel[r];
            unsigned t = (unsigned)(key & 0xFFFFFFFFu);
            unsigned u = (unsigned)(key >> 32);
            scv = finv(~u);           // exact score bits
            lab = (int)(t / K) + 1;
            bx  = g_kb[(size_t)b * CK + t];
        }
        size_t base = ((size_t)b * K + r) * 4;
        fb[base + 0] = bx.x; fb[base + 1] = bx.y;
        fb[base + 2] = bx.z; fb[base + 3] = bx.w;
        fl[(size_t)b * K + r] = (float)lab;
        fs[(size_t)b * K + r] = scv;
    }

    // reset per-class counters for the next graph replay (first-ever call
    // sees zero-initialized device globals)
    for (int i = tid; i < C; i += nt) g_cnt[b * C + i] = 0;
}

// ============================================================
extern "C" void kernel_launch(void* const* d_in, const int* in_sizes, int n_in,
                              void* d_out, int out_size) {
    const float*  bb  = (const float*)d_in[0];   // (32, 4, 15130)
    const float*  sc  = (const float*)d_in[1];   // (32, 81, 15130)
    const float*  sxy = (const float*)d_in[2];   // (1,)
    const float*  swh = (const float*)d_in[3];   // (1,)
    const float4* db  = (const float4*)d_in[4];  // (1, 15130, 4)

    dim3 g1((N_ANCH + 255) / 256, BATCH);
    decode_kernel<<<g1, 256>>>(bb, sc, sxy, swh, db);
    nms_kernel<<<dim3(C, BATCH), 256>>>();
    topk_final_kernel<<<BATCH, 512>>>((float*)d_out);
}

// round 13
// speedup vs baseline: 1.8748x; 1.2662x over previous
#include <cuda_runtime.h>
#include <math.h>

#define N_ANCH 15130
#define BATCH  32
#define NCLS   81
#define C      80      // foreground classes (1..80)
#define K      200
#define CK     (C * K) // 16000
#define CONF   0.05f
#define IOUT   0.5f
#define CAP2   1024    // per-class candidate capacity (counts ~434 +/- 20)

// ---- scratch (device globals; zero-initialized at module load) ----
__device__ float4             g_boxes[BATCH * N_ANCH];          // decoded ltrb
__device__ unsigned long long g_cand[(size_t)BATCH * C * CAP2]; // (~ord(score)<<32)|anchor
__device__ int                g_cnt[BATCH * C];                 // per (b,c) count; re-zeroed by topk each launch
__device__ unsigned           g_u[BATCH * CK];                  // kept keys: ~ord(score), 0xFFFFFFFF = invalid
__device__ float4             g_kb[BATCH * CK];                 // per-class top-k boxes

// monotonic float->uint order map (ascending) and exact inverse
__device__ __forceinline__ unsigned ford(float f) {
    unsigned u = __float_as_uint(f);
    return (u & 0x80000000u) ? ~u : (u | 0x80000000u);
}
__device__ __forceinline__ float finv(unsigned v) {
    unsigned b = (v & 0x80000000u) ? (v & 0x7FFFFFFFu) : ~v;
    return __uint_as_float(b);
}

__device__ __forceinline__ void emit_cand(int cell, float p, unsigned n) {
    int pos = atomicAdd(&g_cnt[cell], 1);
    if (pos < CAP2)
        g_cand[(size_t)cell * CAP2 + pos] =
            ((unsigned long long)(~ford(p)) << 32) | n;
}

// ============================================================
// Kernel 1: box decode + softmax, 2 anchors per thread (float2 loads)
//   pass1 (DRAM): running max     pass2 (L2): exp-sum in class order
//   pass3 (L2):   logit-space prefilter, exact p only for survivors
// Scores are bit-identical to the scalar version (same op order per lane).
// ============================================================
__global__ void __launch_bounds__(256) decode_kernel(
        const float* __restrict__ bb, const float* __restrict__ sc,
        const float* __restrict__ sxy_p, const float* __restrict__ swh_p,
        const float4* __restrict__ db) {
    int t = blockIdx.x * 256 + threadIdx.x;
    int b = blockIdx.y;
    if (t >= N_ANCH / 2) return;   // 15130 even: no tail
    int n = 2 * t;

    float sxy = sxy_p[0], swh = swh_p[0];

    // box decode for anchors n, n+1
    {
        float4 d0 = db[n], d1 = db[n + 1];
        const float* bp = bb + (size_t)b * 4 * N_ANCH + n;
        float2 vx = *(const float2*)(bp);
        float2 vy = *(const float2*)(bp + N_ANCH);
        float2 vw = *(const float2*)(bp + 2 * N_ANCH);
        float2 vh = *(const float2*)(bp + 3 * N_ANCH);

        float x0 = vx.x * sxy * d0.z + d0.x;
        float y0 = vy.x * sxy * d0.w + d0.y;
        float w0 = expf(vw.x * swh) * d0.z;
        float h0 = expf(vh.x * swh) * d0.w;
        g_boxes[(size_t)b * N_ANCH + n] =
            make_float4(x0 - 0.5f * w0, y0 - 0.5f * h0, x0 + 0.5f * w0, y0 + 0.5f * h0);

        float x1 = vx.y * sxy * d1.z + d1.x;
        float y1 = vy.y * sxy * d1.w + d1.y;
        float w1 = expf(vw.y * swh) * d1.z;
        float h1 = expf(vh.y * swh) * d1.w;
        g_boxes[(size_t)b * N_ANCH + n + 1] =
            make_float4(x1 - 0.5f * w1, y1 - 0.5f * h1, x1 + 0.5f * w1, y1 + 0.5f * h1);
    }

    const float* sp = sc + (size_t)b * NCLS * N_ANCH + n;

    // pass 1: max over 81 classes
    float2 v0 = *(const float2*)sp;
    float m0 = v0.x, m1 = v0.y;
#pragma unroll 10
    for (int cc = 1; cc < NCLS; cc++) {
        float2 v = *(const float2*)(sp + (size_t)cc * N_ANCH);
        m0 = fmaxf(m0, v.x); m1 = fmaxf(m1, v.y);
    }

    // pass 2: sum exp(v - m) in class order (single accumulator per lane)
    float s0 = 0.f, s1 = 0.f;
#pragma unroll 9
    for (int cc = 0; cc < NCLS; cc++) {
        float2 v = *(const float2*)(sp + (size_t)cc * N_ANCH);
        s0 += expf(v.x - m0);
        s1 += expf(v.y - m1);
    }
    float i0 = 1.0f / s0, i1 = 1.0f / s1;
    float th0 = m0 + logf(CONF * s0) - 1e-4f;   // loose admit-all prefilter
    float th1 = m1 + logf(CONF * s1) - 1e-4f;

    // pass 3: emit candidates (exact score bits only for rare survivors)
#pragma unroll 8
    for (int cc = 1; cc < NCLS; cc++) {
        float2 v = *(const float2*)(sp + (size_t)cc * N_ANCH);
        if (v.x > th0) {
            float p = expf(v.x - m0) * i0;
            if (p > CONF) emit_cand(b * C + (cc - 1), p, (unsigned)n);
        }
        if (v.y > th1) {
            float p = expf(v.y - m1) * i1;
            if (p > CONF) emit_cand(b * C + (cc - 1), p, (unsigned)(n + 1));
        }
    }
}

// ============================================================
// Kernel 2: per (batch,class): radix-select top-200 -> sort 256 -> bitmask NMS
// ============================================================
__global__ void __launch_bounds__(256, 6) nms_kernel() {
    int c = blockIdx.x, b = blockIdx.y;
    int tid = threadIdx.x; const int nt = 256;
    int lane = tid & 31, wd = tid >> 5;
    int cell = b * C + c;

    __shared__ unsigned hist[256];
    __shared__ unsigned wsum[8];
    __shared__ unsigned s_prefix, s_rank;
    __shared__ int s_nsel;
    __shared__ unsigned long long sel[256];
    __shared__ float4 s_bx[K];
    __shared__ float  s_ar[K];
    __shared__ unsigned long long s_mat[K * 4];   // suppression bitmask rows
    __shared__ unsigned long long s_kp[4];        // keep bits

    int cnt = min(g_cnt[cell], CAP2);

    const unsigned long long* cand = g_cand + (size_t)cell * CAP2;
    const unsigned* candu = (const unsigned*)cand;  // [2*i+1] = upper word

    for (int i = tid; i < K * 4; i += nt) s_mat[i] = 0ull;
    if (tid == 0) { s_prefix = 0; s_rank = K; s_nsel = 0; }
    __syncthreads();

    int nsel;
    if (cnt > 256) {
        // radix select: smallest u (upper 32 of key) with count(<=u) >= K
        for (int pass = 3; pass >= 0; pass--) {
            hist[tid] = 0;
            __syncthreads();
            unsigned prefix = s_prefix;
            int shift = pass * 8;
            unsigned pmask = (pass == 3) ? 0u : (0xFFFFFFFFu << (shift + 8));
            for (int i = tid; i < cnt; i += nt) {
                unsigned u = candu[2 * i + 1];
                if ((u & pmask) == prefix)
                    atomicAdd(&hist[(u >> shift) & 255u], 1u);
            }
            __syncthreads();
            // inclusive prefix over 256 bins
            unsigned x = hist[tid];
            for (int o = 1; o < 32; o <<= 1) {
                unsigned y = __shfl_up_sync(0xFFFFFFFFu, x, o);
                if (lane >= o) x += y;
            }
            if (lane == 31) wsum[wd] = x;
            __syncthreads();
            unsigned off = 0;
            for (int w = 0; w < wd; w++) off += wsum[w];
            unsigned cum = x + off;
            hist[tid] = cum;
            __syncthreads();
            unsigned r = s_rank;
            __syncthreads();   // snapshot rank before winner update
            unsigned prev = tid ? hist[tid - 1] : 0u;
            if (prev < r && cum >= r) {    // exactly one winner
                s_prefix = prefix | ((unsigned)tid << shift);
                s_rank = r - prev;
            }
            __syncthreads();
        }
        unsigned ustar = s_prefix;

        // compact: strict (u < ustar, provably < K of them), then ties (u == ustar)
        for (int i = tid; i < cnt; i += nt) {
            unsigned u = candu[2 * i + 1];
            if (u < ustar) {
                int p = atomicAdd(&s_nsel, 1);
                sel[p] = cand[i];          // p < K always
            }
        }
        __syncthreads();
        for (int i = tid; i < cnt; i += nt) {
            unsigned u = candu[2 * i + 1];
            if (u == ustar) {
                int p = atomicAdd(&s_nsel, 1);
                if (p < 256) sel[p] = cand[i];
            }
        }
        __syncthreads();
        nsel = min(s_nsel, 256);
    } else {
        for (int i = tid; i < cnt; i += nt) sel[i] = cand[i];
        __syncthreads();
        nsel = cnt;
    }

    if (tid >= nsel) sel[tid] = 0xFFFFFFFFFFFFFFFFULL;  // pad
    __syncthreads();

    // bitonic sort 256 ascending on (~ord(score), idx) => score desc, idx asc
    for (int k = 2; k <= 256; k <<= 1) {
        for (int j = k >> 1; j > 0; j >>= 1) {
            int ixj = tid ^ j;
            if (ixj > tid) {
                bool up = ((tid & k) == 0);
                unsigned long long a = sel[tid], d2 = sel[ixj];
                if ((a > d2) == up) { sel[tid] = d2; sel[ixj] = a; }
            }
            __syncthreads();
        }
    }

    int nn = min(nsel, K);
    if (tid < K) {
        if (tid < nn) {
            unsigned idx = (unsigned)(sel[tid] & 0xFFFFFFFFu);
            float4 bx = g_boxes[(size_t)b * N_ANCH + idx];
            s_bx[tid] = bx;
            s_ar[tid] = (bx.z - bx.x) * (bx.w - bx.y);
        } else {
            s_bx[tid] = make_float4(0.f, 0.f, 0.f, 0.f);
            s_ar[tid] = 0.f;
        }
    }
    __syncthreads();

    // parallel IoU suppression matrix: warp per row (i), lanes over j.
    // iou > 0.5  <=>  3*inter > area_i + area_j   (denominator > 0; degenerate
    // zero-area pairs give 0 > 0 = false, matching the reference's NaN > 0.5)
    for (int i = wd; i < nn; i += 8) {
        float4 bi = s_bx[i]; float ai = s_ar[i];
        for (int j = i + 1 + lane; j < nn; j += 32) {
            float4 bj = s_bx[j];
            float w = fminf(bi.z, bj.z) - fmaxf(bi.x, bj.x);
            float h = fminf(bi.w, bj.w) - fmaxf(bi.y, bj.y);
            w = fmaxf(w, 0.f); h = fmaxf(h, 0.f);
            if (3.0f * (w * h) > ai + s_ar[j])
                atomicOr(&s_mat[i * 4 + (j >> 6)], 1ull << (j & 63));
        }
    }
    __syncthreads();

    // serial greedy resolve on one thread (exactly matches reference fori_loop)
    if (tid == 0) {
        unsigned long long r0 = 0, r1 = 0, r2 = 0, r3 = 0;
        unsigned long long k0 = 0, k1 = 0, k2 = 0, k3 = 0;
#define RESOLVE(W, RW, KW)                                              \
        for (int ib = 0; ib < 64; ib++) {                               \
            int i = (W) * 64 + ib;                                      \
            if (i >= nn) break;                                         \
            if (!((RW >> ib) & 1ull)) {                                 \
                KW |= 1ull << ib;                                       \
                r0 |= s_mat[i * 4 + 0]; r1 |= s_mat[i * 4 + 1];         \
                r2 |= s_mat[i * 4 + 2]; r3 |= s_mat[i * 4 + 3];         \
            }                                                           \
        }
        RESOLVE(0, r0, k0) RESOLVE(1, r1, k1) RESOLVE(2, r2, k2) RESOLVE(3, r3, k3)
#undef RESOLVE
        s_kp[0] = k0; s_kp[1] = k1; s_kp[2] = k2; s_kp[3] = k3;
    }
    __syncthreads();

    unsigned* ou  = g_u  + (size_t)b * CK + c * K;
    float4*   okb = g_kb + (size_t)b * CK + c * K;
    if (tid < K) {
        bool valid = (tid < nn) && ((s_kp[tid >> 6] >> (tid & 63)) & 1ull);
        ou[tid]  = valid ? (unsigned)(sel[tid] >> 32) : 0xFFFFFFFFu;
        okb[tid] = s_bx[tid];
    }
}

// ============================================================
// Kernel 3: per image, exact top-200 via radix select (parallel scans)
// ============================================================
__global__ void __launch_bounds__(512) topk_final_kernel(float* __restrict__ out) {
    const int nt = 512;
    int b = blockIdx.x, tid = threadIdx.x;
    int lane = tid & 31, wid = tid >> 5;

    __shared__ unsigned hist[256];
    __shared__ unsigned cum[256];
    __shared__ unsigned wsum[8];
    __shared__ unsigned s_prefix, s_rank, s_ustar, s_V;
    __shared__ int s_done, s_n1, s_n2;
    __shared__ unsigned long long sel[256];
    __shared__ int eqbuf[256];

    const unsigned* up = g_u + (size_t)b * CK;

    if (tid == 0) { s_prefix = 0; s_rank = K; s_done = 0; s_ustar = 0xFFFFFFFFu; s_V = 0; }
    __syncthreads();

    for (int pass = 3; pass >= 0; pass--) {
        for (int i = tid; i < 256; i += nt) hist[i] = 0;
        __syncthreads();
        int done = s_done;
        unsigned prefix = s_prefix;
        int shift = pass * 8;
        unsigned pmask = (pass == 3) ? 0u : (0xFFFFFFFFu << (shift + 8));

        if (!done) {
            for (int t0 = 0; t0 < CK; t0 += nt) {
                int t = t0 + tid;
                unsigned bin = 0xFFFFFFFFu;
                if (t < CK) {
                    unsigned u = up[t];
                    if (u != 0xFFFFFFFFu && (u & pmask) == prefix)
                        bin = (u >> shift) & 255u;
                }
                unsigned peers = __match_any_sync(0xFFFFFFFFu, bin);
                if (bin != 0xFFFFFFFFu && lane == (__ffs(peers) - 1))
                    atomicAdd(&hist[bin], (unsigned)__popc(peers));
            }
        }
        __syncthreads();

        // parallel inclusive prefix over 256 bins
        unsigned x = 0;
        if (tid < 256) {
            x = hist[tid];
            for (int o = 1; o < 32; o <<= 1) {
                unsigned y = __shfl_up_sync(0xFFFFFFFFu, x, o);
                if (lane >= o) x += y;
            }
            if (lane == 31) wsum[wid] = x;
        }
        __syncthreads();
        if (tid < 256) {
            unsigned off = 0;
            for (int w = 0; w < wid; w++) off += wsum[w];
            cum[tid] = x + off;
        }
        __syncthreads();

        if (pass == 3 && tid == 0 && !done) {
            s_V = cum[255];
            if (cum[255] <= (unsigned)K) s_done = 1;   // take all valid
        }
        __syncthreads();
        done = s_done;
        unsigned r = s_rank;
        __syncthreads();   // snapshot rank before winner updates
        if (!done && tid < 256) {
            unsigned prev = tid ? cum[tid - 1] : 0u;
            if (prev < r && cum[tid] >= r) {   // exactly one winner
                unsigned np = prefix | ((unsigned)tid << shift);
                s_prefix = np;
                s_rank = r - prev;
                if (pass == 0) s_ustar = np;
            }
        }
        __syncthreads();
    }

    if (tid == 0) { s_n1 = 0; s_n2 = 0; }
    __syncthreads();
    int done = s_done;
    unsigned ustar = s_ustar;

    // compact strict winners (+ ties at threshold), warp-aggregated
    for (int t0 = 0; t0 < CK; t0 += nt) {
        int t = t0 + tid;
        unsigned u = (t < CK) ? up[t] : 0xFFFFFFFFu;
        bool w1 = (u != 0xFFFFFFFFu) && (done || (u < ustar));
        unsigned m1 = __ballot_sync(0xFFFFFFFFu, w1);
        if (w1) {
            int ldr = __ffs(m1) - 1;
            int base = 0;
            if (lane == ldr) base = atomicAdd(&s_n1, __popc(m1));
            base = __shfl_sync(m1, base, ldr);
            int p = base + __popc(m1 & ((1u << lane) - 1));
            if (p < 256) sel[p] = ((unsigned long long)u << 32) | (unsigned)t;
        }
        bool w2 = (!done) && (u == ustar);
        unsigned m2 = __ballot_sync(0xFFFFFFFFu, w2);
        if (w2) {
            int ldr = __ffs(m2) - 1;
            int base = 0;
            if (lane == ldr) base = atomicAdd(&s_n2, __popc(m2));
            base = __shfl_sync(m2, base, ldr);
            int p = base + __popc(m2 & ((1u << lane) - 1));
            if (p < 256) eqbuf[p] = t;
        }
    }
    __syncthreads();
    int n1 = min(s_n1, 256), n2 = min(s_n2, 256);
    int total;
    if (!done) {
        // resolve ties by lowest index (top_k semantics)
        for (int i = tid; i < 256; i += nt) if (i >= n2) eqbuf[i] = 0x7FFFFFFF;
        __syncthreads();
        for (int k = 2; k <= 256; k <<= 1) {
            for (int j = k >> 1; j > 0; j >>= 1) {
                for (int i = tid; i < 256; i += nt) {
                    int ixj = i ^ j;
                    if (ixj > i) {
                        bool up2 = ((i & k) == 0);
                        int a = eqbuf[i], d2 = eqbuf[ixj];
                        if ((a > d2) == up2) { eqbuf[i] = d2; eqbuf[ixj] = a; }
                    }
                }
                __syncthreads();
            }
        }
        int need = K - n1;
        if (tid < need)
            sel[n1 + tid] = ((unsigned long long)ustar << 32) | (unsigned)eqbuf[tid];
        total = K;
    } else {
        total = n1;   // == V <= K
    }
    __syncthreads();
    for (int i = tid; i < 256; i += nt) if (i >= total) sel[i] = 0xFFFFFFFFFFFFFFFFULL;
    __syncthreads();

    // final sort of <=200 selected: (score desc, idx asc)
    for (int k = 2; k <= 256; k <<= 1) {
        for (int j = k >> 1; j > 0; j >>= 1) {
            for (int i = tid; i < 256; i += nt) {
                int ixj = i ^ j;
                if (ixj > i) {
                    bool up2 = ((i & k) == 0);
                    unsigned long long a = sel[i], d2 = sel[ixj];
                    if ((a > d2) == up2) { sel[i] = d2; sel[ixj] = a; }
                }
            }
            __syncthreads();
        }
    }

    // outputs concatenated: fb[B][K][4], fl[B][K], fs[B][K]
    float* fb = out;
    float* fl = out + (size_t)BATCH * K * 4;
    float* fs = fl + (size_t)BATCH * K;

    for (int r = tid; r < K; r += nt) {
        float4 bx = make_float4(0.f, 0.f, 0.f, 0.f);
        float scv = 0.f; int lab = 0;
        if (r < total) {
            unsigned long long key = sel[r];
            unsigned t = (unsigned)(key & 0xFFFFFFFFu);
            unsigned u = (unsigned)(key >> 32);
            scv = finv(~u);           // exact score bits
            lab = (int)(t / K) + 1;
            bx  = g_kb[(size_t)b * CK + t];
        }
        size_t base = ((size_t)b * K + r) * 4;
        fb[base + 0] = bx.x; fb[base + 1] = bx.y;
        fb[base + 2] = bx.z; fb[base + 3] = bx.w;
        fl[(size_t)b * K + r] = (float)lab;
        fs[(size_t)b * K + r] = scv;
    }

    // reset per-class counters for the next graph replay (first-ever call
    // sees zero-initialized device globals)
    for (int i = tid; i < C; i += nt) g_cnt[b * C + i] = 0;
}

// ============================================================
extern "C" void kernel_launch(void* const* d_in, const int* in_sizes, int n_in,
                              void* d_out, int out_size) {
    const float*  bb  = (const float*)d_in[0];   // (32, 4, 15130)
    const float*  sc  = (const float*)d_in[1];   // (32, 81, 15130)
    const float*  sxy = (const float*)d_in[2];   // (1,)
    const float*  swh = (const float*)d_in[3];   // (1,)
    const float4* db  = (const float4*)d_in[4];  // (1, 15130, 4)

    dim3 g1((N_ANCH / 2 + 255) / 256, BATCH);
    decode_kernel<<<g1, 256>>>(bb, sc, sxy, swh, db);
    nms_kernel<<<dim3(C, BATCH), 256>>>();
    topk_final_kernel<<<BATCH, 512>>>((float*)d_out);
}